// round 3
// baseline (speedup 1.0000x reference)
#include <cuda_runtime.h>
#include <math.h>

#define BSZ 4
#define SEQ 256
#define DM  128
#define NH  8
#define DK  16
#define NKN 16
#define NEGF (-1e32f)

// ---------------- scratch (device globals; no allocation allowed) ----------------
__device__ float g_Q1[BSZ*SEQ*DM];
__device__ float g_V1[BSZ*SEQ*DM];
__device__ float g_A1[BSZ*SEQ*DM];
__device__ float g_P [BSZ*SEQ*DM];
__device__ float g_K2[BSZ*SEQ*DM];
__device__ float g_V2[BSZ*SEQ*DM];
__device__ float g_Q2[NKN*DM];
__device__ float g_A2[BSZ*NKN*SEQ*DM];

// ---------------- warp helpers ----------------
__device__ __forceinline__ float wmax(float v){
    #pragma unroll
    for (int o=16;o>0;o>>=1) v = fmaxf(v, __shfl_xor_sync(0xffffffffu, v, o));
    return v;
}
__device__ __forceinline__ float wsum(float v){
    #pragma unroll
    for (int o=16;o>0;o>>=1) v += __shfl_xor_sync(0xffffffffu, v, o);
    return v;
}
__device__ __forceinline__ float wscan_incl(float x, int lane){
    #pragma unroll
    for (int o=1;o<32;o<<=1){
        float y = __shfl_up_sync(0xffffffffu, x, o);
        if (lane >= o) x += y;
    }
    return x;
}

// ---------------- batched projection: Y[M,128] = X[M,128] @ W^T + b ----------------
struct ProjSet {
    const float* X; const float* W; const float* B; float* Y; int M;
};

__device__ __forceinline__ void proj_body(const float* __restrict__ X,
                                          const float* __restrict__ W,
                                          const float* __restrict__ bias,
                                          float* __restrict__ Y, int M,
                                          float* sh)
{
    float* WsT = sh;                 // [128*129]
    float* Ash = sh + 128*129;       // [8*128]
    const int t = threadIdx.x;       // 128 threads
    const int row0 = blockIdx.x * 8;
    if (row0 >= M) return;           // uniform per block; safe w.r.t. barriers

    for (int idx=t; idx<DM*DM; idx+=128){
        int n = idx >> 7, k = idx & 127;
        WsT[k*129 + n] = W[idx];
    }
    for (int idx=t; idx<8*DM; idx+=128){
        int r = idx >> 7, c = idx & 127;
        int row = row0 + r;
        Ash[idx] = (row < M) ? X[(size_t)row*DM + c] : 0.f;
    }
    __syncthreads();

    float acc[8];
    #pragma unroll
    for (int r=0;r<8;r++) acc[r] = 0.f;

    for (int k=0;k<DM;k+=4){
        float w0 = WsT[(k+0)*129 + t];
        float w1 = WsT[(k+1)*129 + t];
        float w2 = WsT[(k+2)*129 + t];
        float w3 = WsT[(k+3)*129 + t];
        #pragma unroll
        for (int r=0;r<8;r++){
            float4 a = *(const float4*)&Ash[r*DM + k];
            acc[r] += a.x*w0 + a.y*w1 + a.z*w2 + a.w*w3;
        }
    }
    float bv = bias[t];
    #pragma unroll
    for (int r=0;r<8;r++){
        int row = row0 + r;
        if (row < M) Y[(size_t)row*DM + t] = acc[r] + bv;
    }
}

__global__ void proj4_kernel(ProjSet s0, ProjSet s1, ProjSet s2, ProjSet s3)
{
    extern __shared__ float sh[];
    ProjSet s;
    switch (blockIdx.y){
        case 0: s = s0; break;
        case 1: s = s1; break;
        case 2: s = s2; break;
        default: s = s3; break;
    }
    proj_body(s.X, s.W, s.B, s.Y, s.M, sh);
}

__global__ void proj_kernel(const float* __restrict__ X, const float* __restrict__ W,
                            const float* __restrict__ bias, float* __restrict__ Y, int M)
{
    extern __shared__ float sh[];
    proj_body(X, W, bias, Y, M, sh);
}

// ---------------- layer-1 attention ----------------
// q == k (kq_same). mask: j <= i (peek_cur). maxout = false.
// grid: (4 chunks, 32 b*h), block 256.
__global__ void attn1_kernel(const float* __restrict__ Q1, const float* __restrict__ V1,
                             const float* __restrict__ gamma, float* __restrict__ qsc,
                             float* __restrict__ A1)
{
    __shared__ __align__(16) float KshT[DK*SEQ];   // [d][j]
    __shared__ __align__(16) float Vsh[SEQ*20];    // [j][20] padded
    __shared__ float orow[8][16];

    const int chunk = blockIdx.x;      // 0..3
    const int bh    = blockIdx.y;      // 0..31
    const int b = bh >> 3, h = bh & 7;
    const int tid = threadIdx.x, lane = tid & 31, w = tid >> 5;

    for (int idx=tid; idx<SEQ*DK; idx+=256){
        int j = idx >> 4, d = idx & 15;
        size_t g = (size_t)(b*SEQ + j)*DM + h*DK + d;
        KshT[d*SEQ + j] = Q1[g];
        Vsh[j*20 + d]   = V1[g];
    }
    __syncthreads();

    const float gdec = fabsf(gamma[h]);

    for (int r=0;r<8;r++){
        const int i = (chunk*8 + w) + 32*r;
        const int last = i, tmax = last >> 5;

        float q[DK];
        #pragma unroll
        for (int d=0;d<DK;d++) q[d] = KshT[d*SEQ + i];

        float sc[8], e[8], cum[8], p2[8];

        // scores over active groups
        #pragma unroll
        for (int t=0;t<8;t++) if (t<=tmax){
            int j = t*32 + lane;
            float s = 0.f;
            #pragma unroll
            for (int d=0;d<DK;d++) s += q[d]*KshT[d*SEQ + j];
            sc[t] = s * 0.25f;
        }
        // softmax #1
        float m1 = NEGF;
        #pragma unroll
        for (int t=0;t<8;t++) if (t<=tmax){
            int j = t*32 + lane;
            m1 = fmaxf(m1, (j<=last) ? sc[t] : NEGF);
        }
        m1 = wmax(m1);
        float sum1 = 0.f;
        #pragma unroll
        for (int t=0;t<8;t++) if (t<=tmax){
            int j = t*32 + lane;
            float ev = (j<=last) ? expf(sc[t]-m1) : 0.f;
            e[t] = ev; sum1 += ev;
        }
        sum1 = wsum(sum1);
        // inclusive cumsum of e over j
        float carry = 0.f;
        #pragma unroll
        for (int t=0;t<8;t++) if (t<=tmax){
            float x = wscan_incl(e[t], lane);
            cum[t] = x + carry;
            carry += __shfl_sync(0xffffffffu, x, 31);
        }
        const float Te = carry;
        const float inv1 = 1.0f / sum1;

        // time-decay effect + masked scores #2
        float m2 = NEGF;
        #pragma unroll
        for (int t=0;t<8;t++) if (t<=tmax){
            int j = t*32 + lane;
            float rem = fmaxf((Te - cum[t]) * inv1, 0.f);
            float pos = fabsf((float)(i - j));
            float dist = sqrtf(rem * pos);
            float eff = expf(-gdec * dist);
            eff = fminf(fmaxf(eff, 1e-5f), 1e5f);
            float v = sc[t] * eff;
            e[t] = v;                      // reuse as sc2
            m2 = fmaxf(m2, (j<=last) ? v : NEGF);
        }
        m2 = wmax(m2);
        float sum2 = 0.f;
        #pragma unroll
        for (int t=0;t<8;t++) if (t<=tmax){
            int j = t*32 + lane;
            float e2 = (j<=last) ? expf(e[t]-m2) : 0.f;
            e[t] = e2; sum2 += e2;
        }
        sum2 = wsum(sum2);
        const float inv2 = 1.0f / sum2;
        #pragma unroll
        for (int t=0;t<8;t++) p2[t] = (t<=tmax) ? e[t]*inv2 : 0.f;

        // write q_scores row (fully, zeros beyond mask)
        float* qrow = qsc + ((size_t)(b*NH + h)*SEQ + i)*SEQ;
        #pragma unroll
        for (int t=0;t<8;t++) qrow[t*32 + lane] = p2[t];

        // out = p2 @ V
        float o[16];
        #pragma unroll
        for (int d=0;d<16;d++) o[d] = 0.f;
        #pragma unroll
        for (int t=0;t<8;t++) if (t<=tmax){
            int j = t*32 + lane;
            float p = p2[t];
            float4 v0 = *(const float4*)&Vsh[j*20 + 0];
            float4 v1 = *(const float4*)&Vsh[j*20 + 4];
            float4 v2 = *(const float4*)&Vsh[j*20 + 8];
            float4 v3 = *(const float4*)&Vsh[j*20 + 12];
            o[0]+=p*v0.x; o[1]+=p*v0.y; o[2]+=p*v0.z; o[3]+=p*v0.w;
            o[4]+=p*v1.x; o[5]+=p*v1.y; o[6]+=p*v1.z; o[7]+=p*v1.w;
            o[8]+=p*v2.x; o[9]+=p*v2.y; o[10]+=p*v2.z; o[11]+=p*v2.w;
            o[12]+=p*v3.x; o[13]+=p*v3.y; o[14]+=p*v3.z; o[15]+=p*v3.w;
        }
        #pragma unroll
        for (int d=0;d<16;d++){
            float v = wsum(o[d]);
            if (lane == 0) orow[w][d] = v;
        }
        __syncwarp();
        if (lane < 16) A1[((size_t)(b*SEQ + i))*DM + h*DK + lane] = orow[w][lane];
        __syncwarp();
    }
}

// ---------------- layer-2 attention ----------------
// Queries constant over rows -> base scores s_j once per block; first softmax via
// shared prefix sums. mask: j < i (strict). maxout = true (scale = min(sum2,5)).
// grid: 512 = (b, n, h), block 256.
__global__ void attn2_kernel(const float* __restrict__ K2, const float* __restrict__ V2,
                             const float* __restrict__ Q2, const float* __restrict__ gamma,
                             float* __restrict__ ksc, float* __restrict__ A2)
{
    __shared__ __align__(16) float KshT[DK*SEQ];
    __shared__ __align__(16) float Vsh[SEQ*20];
    __shared__ float ss[SEQ];
    __shared__ float Ce[SEQ];
    __shared__ float wred[8];
    __shared__ float orow[8][16];

    const int bid = blockIdx.x;
    const int b = bid >> 7, n = (bid >> 3) & 15, h = bid & 7;
    const int tid = threadIdx.x, lane = tid & 31, w = tid >> 5;

    for (int idx=tid; idx<SEQ*DK; idx+=256){
        int j = idx >> 4, d = idx & 15;
        size_t g = (size_t)(b*SEQ + j)*DM + h*DK + d;
        KshT[d*SEQ + j] = K2[g];
        Vsh[j*20 + d]   = V2[g];
    }
    __syncthreads();

    float q[DK];
    #pragma unroll
    for (int d=0;d<DK;d++) q[d] = Q2[n*DM + h*DK + d];

    // base scores s_j (one per thread)
    float s = 0.f;
    #pragma unroll
    for (int d=0;d<DK;d++) s += q[d]*KshT[d*SEQ + tid];
    s *= 0.25f;
    ss[tid] = s;

    float m = wmax(s);
    if (lane == 0) wred[w] = m;
    __syncthreads();
    float bmax = wred[0];
    #pragma unroll
    for (int k=1;k<8;k++) bmax = fmaxf(bmax, wred[k]);
    float e = expf(s - bmax);
    float x = wscan_incl(e, lane);
    __syncthreads();
    if (lane == 31) wred[w] = x;
    __syncthreads();
    float off = 0.f;
    for (int k=0;k<w;k++) off += wred[k];
    Ce[tid] = x + off;             // inclusive prefix sum of e
    __syncthreads();

    const float gdec = fabsf(gamma[h]);

    for (int r=0;r<32;r++){
        const int i = w + 8*r;
        float* krow = ksc + (((size_t)(b*NH + h)*SEQ + i)*NKN + n)*SEQ;
        if (i == 0){
            #pragma unroll
            for (int t=0;t<8;t++) krow[t*32 + lane] = 0.f;
            if (lane < 16) A2[((size_t)((b*NKN + n)*SEQ + 0))*DM + h*DK + lane] = 0.f;
            continue;
        }
        const int last = i - 1, tmax = last >> 5;
        const float invS = 1.0f / Ce[last];

        float sc2[8];
        float m2 = NEGF;
        #pragma unroll
        for (int t=0;t<8;t++) if (t<=tmax){
            int j = t*32 + lane;
            float rem = fmaxf(1.0f - Ce[j]*invS, 0.f);
            float pos = fabsf((float)(i - j));
            float dist = sqrtf(rem * pos);
            float eff = expf(-gdec * dist);
            eff = fminf(fmaxf(eff, 1e-5f), 1e5f);
            float v = ss[j] * eff;
            sc2[t] = v;
            m2 = fmaxf(m2, (j<=last) ? v : NEGF);
        }
        m2 = wmax(m2);
        float sum2 = 0.f;
        #pragma unroll
        for (int t=0;t<8;t++) if (t<=tmax){
            int j = t*32 + lane;
            float e2 = (j<=last) ? expf(sc2[t]-m2) : 0.f;
            sc2[t] = e2; sum2 += e2;
        }
        sum2 = wsum(sum2);
        // maxout: max(p2) = 1/sum2 -> scale = min(sum2, 5)
        const float coef = fminf(sum2, 5.0f) / sum2;

        float o[16];
        #pragma unroll
        for (int d=0;d<16;d++) o[d] = 0.f;
        #pragma unroll
        for (int t=0;t<8;t++){
            float p = (t<=tmax) ? sc2[t]*coef : 0.f;
            krow[t*32 + lane] = p;
            if (t<=tmax){
                int j = t*32 + lane;
                float4 v0 = *(const float4*)&Vsh[j*20 + 0];
                float4 v1 = *(const float4*)&Vsh[j*20 + 4];
                float4 v2 = *(const float4*)&Vsh[j*20 + 8];
                float4 v3 = *(const float4*)&Vsh[j*20 + 12];
                o[0]+=p*v0.x; o[1]+=p*v0.y; o[2]+=p*v0.z; o[3]+=p*v0.w;
                o[4]+=p*v1.x; o[5]+=p*v1.y; o[6]+=p*v1.z; o[7]+=p*v1.w;
                o[8]+=p*v2.x; o[9]+=p*v2.y; o[10]+=p*v2.z; o[11]+=p*v2.w;
                o[12]+=p*v3.x; o[13]+=p*v3.y; o[14]+=p*v3.z; o[15]+=p*v3.w;
            }
        }
        #pragma unroll
        for (int d=0;d<16;d++){
            float v = wsum(o[d]);
            if (lane == 0) orow[w][d] = v;
        }
        __syncwarp();
        if (lane < 16) A2[((size_t)((b*NKN + n)*SEQ + i))*DM + h*DK + lane] = orow[w][lane];
        __syncwarp();
    }
}

// ---------------- out-proj + residual + layernorm ----------------
__global__ void outln1_kernel(const float* __restrict__ Ain, const float* __restrict__ W,
                              const float* __restrict__ bias, const float* __restrict__ Res,
                              const float* __restrict__ lg, const float* __restrict__ lb,
                              float* __restrict__ Y)
{
    extern __shared__ float sh[];
    float* WsT = sh;
    float* Ash = sh + 128*129;
    __shared__ float red1[4], red2[4];
    const int t = threadIdx.x, lane = t & 31, w = t >> 5;
    const int row0 = blockIdx.x * 8;

    for (int idx=t; idx<DM*DM; idx+=128){
        int n = idx >> 7, k = idx & 127;
        WsT[k*129 + n] = W[idx];
    }
    for (int idx=t; idx<8*DM; idx+=128){
        int r = idx >> 7, c = idx & 127;
        Ash[idx] = Ain[(size_t)(row0 + r)*DM + c];
    }
    __syncthreads();

    float acc[8];
    #pragma unroll
    for (int r=0;r<8;r++) acc[r] = 0.f;
    for (int k=0;k<DM;k+=4){
        float w0 = WsT[(k+0)*129 + t];
        float w1 = WsT[(k+1)*129 + t];
        float w2 = WsT[(k+2)*129 + t];
        float w3 = WsT[(k+3)*129 + t];
        #pragma unroll
        for (int r=0;r<8;r++){
            float4 a = *(const float4*)&Ash[r*DM + k];
            acc[r] += a.x*w0 + a.y*w1 + a.z*w2 + a.w*w3;
        }
    }
    const float bv = bias[t], gv = lg[t], bb = lb[t];
    for (int r=0;r<8;r++){
        int row = row0 + r;
        float y = acc[r] + bv + Res[(size_t)row*DM + t];
        float sg = wsum(y), sq = wsum(y*y);
        if (lane == 0){ red1[w] = sg; red2[w] = sq; }
        __syncthreads();
        float tot = red1[0]+red1[1]+red1[2]+red1[3];
        float tq  = red2[0]+red2[1]+red2[2]+red2[3];
        __syncthreads();
        float mean = tot * (1.f/128.f);
        float var  = fmaxf(tq * (1.f/128.f) - mean*mean, 0.f);
        float outv = (y - mean) * rsqrtf(var + 1e-5f) * gv + bb;
        Y[(size_t)row*DM + t] = outv;
    }
}

__global__ void outln2_kernel(const float* __restrict__ Ain, const float* __restrict__ W,
                              const float* __restrict__ bias, const float* __restrict__ Know,
                              const float* __restrict__ lg, const float* __restrict__ lb,
                              float* __restrict__ Z)
{
    extern __shared__ float sh[];
    float* WsT = sh;
    float* Ash = sh + 128*129;
    __shared__ float red1[4], red2[4];
    const int t = threadIdx.x, lane = t & 31, w = t >> 5;
    const int row0 = blockIdx.x * 8;

    for (int idx=t; idx<DM*DM; idx+=128){
        int n = idx >> 7, k = idx & 127;
        WsT[k*129 + n] = W[idx];
    }
    for (int idx=t; idx<8*DM; idx+=128){
        int r = idx >> 7, c = idx & 127;
        Ash[idx] = Ain[(size_t)(row0 + r)*DM + c];
    }
    __syncthreads();

    float acc[8];
    #pragma unroll
    for (int r=0;r<8;r++) acc[r] = 0.f;
    for (int k=0;k<DM;k+=4){
        float w0 = WsT[(k+0)*129 + t];
        float w1 = WsT[(k+1)*129 + t];
        float w2 = WsT[(k+2)*129 + t];
        float w3 = WsT[(k+3)*129 + t];
        #pragma unroll
        for (int r=0;r<8;r++){
            float4 a = *(const float4*)&Ash[r*DM + k];
            acc[r] += a.x*w0 + a.y*w1 + a.z*w2 + a.w*w3;
        }
    }
    const float bv = bias[t], gv = lg[t], bb = lb[t];
    for (int r=0;r<8;r++){
        int row = row0 + r;                 // row = (b*NK + n)*SEQ + i
        int nn = (row >> 8) & 15;
        int bI = row >> 12;
        int ii = row & 255;
        float y = acc[r] + bv + Know[nn*DM + t];
        float sg = wsum(y), sq = wsum(y*y);
        if (lane == 0){ red1[w] = sg; red2[w] = sq; }
        __syncthreads();
        float tot = red1[0]+red1[1]+red1[2]+red1[3];
        float tq  = red2[0]+red2[1]+red2[2]+red2[3];
        __syncthreads();
        float mean = tot * (1.f/128.f);
        float var  = fmaxf(tq * (1.f/128.f) - mean*mean, 0.f);
        float outv = (y - mean) * rsqrtf(var + 1e-5f) * gv + bb;
        Z[((size_t)(bI*SEQ + ii))*(NKN*DM) + nn*DM + t] = outv;
    }
}

// ---------------- launch ----------------
extern "C" void kernel_launch(void* const* d_in, const int* in_sizes, int n_in,
                              void* d_out, int out_size)
{
    const float* q_emb   = (const float*)d_in[0];
    const float* s_emb   = (const float*)d_in[1];
    const float* b1_Wq   = (const float*)d_in[3];
    const float* b1_bq   = (const float*)d_in[4];
    const float* b1_Wv   = (const float*)d_in[5];
    const float* b1_bv   = (const float*)d_in[6];
    const float* b1_Wo   = (const float*)d_in[7];
    const float* b1_bo   = (const float*)d_in[8];
    const float* b1_gam  = (const float*)d_in[9];
    const float* b1_lng  = (const float*)d_in[10];
    const float* b1_lnb  = (const float*)d_in[11];
    const float* b4_Wq   = (const float*)d_in[12];
    const float* b4_bq   = (const float*)d_in[13];
    const float* b4_Wk   = (const float*)d_in[14];
    const float* b4_bk   = (const float*)d_in[15];
    const float* b4_Wv   = (const float*)d_in[16];
    const float* b4_bv   = (const float*)d_in[17];
    const float* b4_Wo   = (const float*)d_in[18];
    const float* b4_bo   = (const float*)d_in[19];
    const float* b4_gam  = (const float*)d_in[20];
    const float* b4_lng  = (const float*)d_in[21];
    const float* b4_lnb  = (const float*)d_in[22];
    const float* know    = (const float*)d_in[23];

    float* out = (float*)d_out;
    float* z   = out;                                     // [BS,S,NK*D]
    float* qsc = out + (size_t)BSZ*SEQ*NKN*DM;            // [BS,H,S,S]
    float* ksc = qsc + (size_t)BSZ*NH*SEQ*SEQ;            // [BS,H,S,NK,S]

    float *pQ1,*pV1,*pA1,*pP,*pK2,*pV2,*pQ2,*pA2;
    cudaGetSymbolAddress((void**)&pQ1, g_Q1);
    cudaGetSymbolAddress((void**)&pV1, g_V1);
    cudaGetSymbolAddress((void**)&pA1, g_A1);
    cudaGetSymbolAddress((void**)&pP,  g_P);
    cudaGetSymbolAddress((void**)&pK2, g_K2);
    cudaGetSymbolAddress((void**)&pV2, g_V2);
    cudaGetSymbolAddress((void**)&pQ2, g_Q2);
    cudaGetSymbolAddress((void**)&pA2, g_A2);

    const size_t SH = (size_t)(128*129 + 8*128) * sizeof(float);  // 70144 B
    cudaFuncSetAttribute(proj4_kernel,  cudaFuncAttributeMaxDynamicSharedMemorySize, (int)SH);
    cudaFuncSetAttribute(proj_kernel,   cudaFuncAttributeMaxDynamicSharedMemorySize, (int)SH);
    cudaFuncSetAttribute(outln1_kernel, cudaFuncAttributeMaxDynamicSharedMemorySize, (int)SH);
    cudaFuncSetAttribute(outln2_kernel, cudaFuncAttributeMaxDynamicSharedMemorySize, (int)SH);

    const int MROWS = BSZ*SEQ;  // 1024

    // input-only projections in ONE launch: Q1(=K1), V1, K2, Q2
    ProjSet sQ1 = { q_emb, b1_Wq, b1_bq, pQ1, MROWS };
    ProjSet sV1 = { s_emb, b1_Wv, b1_bv, pV1, MROWS };
    ProjSet sK2 = { q_emb, b4_Wk, b4_bk, pK2, MROWS };
    ProjSet sQ2 = { know,  b4_Wq, b4_bq, pQ2, NKN   };
    proj4_kernel<<<dim3(MROWS/8, 4), 128, SH>>>(sQ1, sV1, sK2, sQ2);

    // layer 1 attention + epilogue
    attn1_kernel<<<dim3(4,32), 256>>>(pQ1, pV1, b1_gam, qsc, pA1);
    outln1_kernel<<<MROWS/8, 128, SH>>>(pA1, b1_Wo, b1_bo, q_emb, b1_lng, b1_lnb, pP);

    // layer 2 V projection (depends on P)
    proj_kernel<<<MROWS/8, 128, SH>>>(pP, b4_Wv, b4_bv, pV2, MROWS);

    // layer 2 attention + epilogue
    attn2_kernel<<<512, 256>>>(pK2, pV2, pQ2, b4_gam, ksc, pA2);
    outln2_kernel<<<(BSZ*NKN*SEQ)/8, 128, SH>>>(pA2, b4_Wo, b4_bo, know, b4_lng, b4_lnb, z);
}

// round 4
// speedup vs baseline: 1.4729x; 1.4729x over previous
#include <cuda_runtime.h>
#include <math.h>

#define BSZ 4
#define SEQ 256
#define DM  128
#define NH  8
#define DK  16
#define NKN 16
#define NEGF (-1e32f)

// ---------------- scratch (device globals; no allocation allowed) ----------------
__device__ float g_Q1[BSZ*SEQ*DM];
__device__ float g_V1[BSZ*SEQ*DM];
__device__ float g_A1[BSZ*SEQ*DM];
__device__ float g_K2[BSZ*SEQ*DM];
__device__ float g_V2[BSZ*SEQ*DM];
__device__ float g_Q2[NKN*DM];
__device__ float g_A2[BSZ*NKN*SEQ*DM];
__device__ float g_WT[7*DM*DM];   // 0:b1_Wq 1:b1_Wv 2:b1_Wo 3:b4_Wq 4:b4_Wk 5:b4_Wv 6:b4_Wo

// ---------------- warp helpers ----------------
__device__ __forceinline__ float wmax(float v){
    #pragma unroll
    for (int o=16;o>0;o>>=1) v = fmaxf(v, __shfl_xor_sync(0xffffffffu, v, o));
    return v;
}
__device__ __forceinline__ float wsum(float v){
    #pragma unroll
    for (int o=16;o>0;o>>=1) v += __shfl_xor_sync(0xffffffffu, v, o);
    return v;
}
__device__ __forceinline__ float wscan_incl(float x, int lane){
    #pragma unroll
    for (int o=1;o<32;o<<=1){
        float y = __shfl_up_sync(0xffffffffu, x, o);
        if (lane >= o) x += y;
    }
    return x;
}

// ---------------- weight transpose: WT[k][n] = W[n][k] ----------------
struct WPtrs { const float* w[7]; };

__global__ void wt_kernel(WPtrs ws, float* __restrict__ WT)
{
    __shared__ float s[32][33];
    const int m  = blockIdx.y;
    const int bx = blockIdx.x;              // 0..15 -> 4x4 tiles
    const int r0 = (bx & 3) * 32, c0 = (bx >> 2) * 32;
    const int tx = threadIdx.x, ty = threadIdx.y;   // 32 x 8
    const float* src = ws.w[m];
    float* dst = WT + m*DM*DM;

    #pragma unroll
    for (int i=0;i<4;i++)
        s[ty+8*i][tx] = src[(r0+ty+8*i)*DM + c0+tx];
    __syncthreads();
    #pragma unroll
    for (int i=0;i<4;i++)
        dst[(c0+ty+8*i)*DM + r0+tx] = s[tx][ty+8*i];
}

// ---------------- batched projection (WT streaming): Y = X @ W^T + b ----------------
struct ProjSet { const float* X; int wsel; const float* B; float* Y; int M; };

__global__ void proj4_kernel(ProjSet s0, ProjSet s1, ProjSet s2, ProjSet s3,
                             const float* __restrict__ WTbase)
{
    __shared__ float Ash[8*DM];
    ProjSet s;
    switch (blockIdx.y){
        case 0: s = s0; break;
        case 1: s = s1; break;
        case 2: s = s2; break;
        default: s = s3; break;
    }
    const int t = threadIdx.x;             // 128
    const int row0 = blockIdx.x * 8;
    if (row0 >= s.M) return;               // uniform per block

    const float* __restrict__ WT = WTbase + s.wsel*DM*DM;

    #pragma unroll
    for (int r=0;r<8;r++){
        int row = row0 + r;
        Ash[r*DM + t] = (row < s.M) ? s.X[(size_t)row*DM + t] : 0.f;
    }
    __syncthreads();

    float acc[8];
    #pragma unroll
    for (int r=0;r<8;r++) acc[r] = 0.f;

    for (int k=0;k<DM;k+=8){
        float w0 = WT[(k+0)*DM + t];
        float w1 = WT[(k+1)*DM + t];
        float w2 = WT[(k+2)*DM + t];
        float w3 = WT[(k+3)*DM + t];
        float w4 = WT[(k+4)*DM + t];
        float w5 = WT[(k+5)*DM + t];
        float w6 = WT[(k+6)*DM + t];
        float w7 = WT[(k+7)*DM + t];
        #pragma unroll
        for (int r=0;r<8;r++){
            float4 a0 = *(const float4*)&Ash[r*DM + k];
            float4 a1 = *(const float4*)&Ash[r*DM + k + 4];
            acc[r] += a0.x*w0 + a0.y*w1 + a0.z*w2 + a0.w*w3
                    + a1.x*w4 + a1.y*w5 + a1.z*w6 + a1.w*w7;
        }
    }
    const float bv = s.B[t];
    #pragma unroll
    for (int r=0;r<8;r++){
        int row = row0 + r;
        if (row < s.M) s.Y[(size_t)row*DM + t] = acc[r] + bv;
    }
}

// ---------------- layer-1 attention ----------------
// q == k (kq_same). mask: j <= i (peek_cur). maxout = false.
// grid: (8 chunks, 32 b*h), block 256, 4 rows per warp.
__global__ void attn1_kernel(const float* __restrict__ Q1, const float* __restrict__ V1,
                             const float* __restrict__ gamma, float* __restrict__ qsc,
                             float* __restrict__ A1)
{
    __shared__ __align__(16) float KshT[DK*SEQ];   // [d][j]
    __shared__ __align__(16) float Vsh[SEQ*20];    // [j][20] padded
    __shared__ float orow[8][16];

    const int chunk = blockIdx.x;      // 0..7
    const int bh    = blockIdx.y;      // 0..31
    const int b = bh >> 3, h = bh & 7;
    const int tid = threadIdx.x, lane = tid & 31, w = tid >> 5;

    for (int idx=tid; idx<SEQ*DK; idx+=256){
        int j = idx >> 4, d = idx & 15;
        size_t g = (size_t)(b*SEQ + j)*DM + h*DK + d;
        KshT[d*SEQ + j] = Q1[g];
        Vsh[j*20 + d]   = V1[g];
    }
    __syncthreads();

    const float gdec = fabsf(gamma[h]);

    for (int r=0;r<4;r++){
        const int i = (chunk*8 + w) + 64*r;
        const int last = i, tmax = last >> 5;

        float q[DK];
        #pragma unroll
        for (int d=0;d<DK;d++) q[d] = KshT[d*SEQ + i];

        float sc[8], e[8], cum[8], p2[8];

        #pragma unroll
        for (int t=0;t<8;t++) if (t<=tmax){
            int j = t*32 + lane;
            float s = 0.f;
            #pragma unroll
            for (int d=0;d<DK;d++) s += q[d]*KshT[d*SEQ + j];
            sc[t] = s * 0.25f;
        }
        float m1 = NEGF;
        #pragma unroll
        for (int t=0;t<8;t++) if (t<=tmax){
            int j = t*32 + lane;
            m1 = fmaxf(m1, (j<=last) ? sc[t] : NEGF);
        }
        m1 = wmax(m1);
        float sum1 = 0.f;
        #pragma unroll
        for (int t=0;t<8;t++) if (t<=tmax){
            int j = t*32 + lane;
            float ev = (j<=last) ? expf(sc[t]-m1) : 0.f;
            e[t] = ev; sum1 += ev;
        }
        sum1 = wsum(sum1);
        float carry = 0.f;
        #pragma unroll
        for (int t=0;t<8;t++) if (t<=tmax){
            float x = wscan_incl(e[t], lane);
            cum[t] = x + carry;
            carry += __shfl_sync(0xffffffffu, x, 31);
        }
        const float Te = carry;
        const float inv1 = 1.0f / sum1;

        float m2 = NEGF;
        #pragma unroll
        for (int t=0;t<8;t++) if (t<=tmax){
            int j = t*32 + lane;
            float rem = fmaxf((Te - cum[t]) * inv1, 0.f);
            float pos = fabsf((float)(i - j));
            float dist = sqrtf(rem * pos);
            float eff = expf(-gdec * dist);
            eff = fminf(fmaxf(eff, 1e-5f), 1e5f);
            float v = sc[t] * eff;
            e[t] = v;
            m2 = fmaxf(m2, (j<=last) ? v : NEGF);
        }
        m2 = wmax(m2);
        float sum2 = 0.f;
        #pragma unroll
        for (int t=0;t<8;t++) if (t<=tmax){
            int j = t*32 + lane;
            float e2 = (j<=last) ? expf(e[t]-m2) : 0.f;
            e[t] = e2; sum2 += e2;
        }
        sum2 = wsum(sum2);
        const float inv2 = 1.0f / sum2;
        #pragma unroll
        for (int t=0;t<8;t++) p2[t] = (t<=tmax) ? e[t]*inv2 : 0.f;

        float* qrow = qsc + ((size_t)(b*NH + h)*SEQ + i)*SEQ;
        #pragma unroll
        for (int t=0;t<8;t++) qrow[t*32 + lane] = p2[t];

        float o[16];
        #pragma unroll
        for (int d=0;d<16;d++) o[d] = 0.f;
        #pragma unroll
        for (int t=0;t<8;t++) if (t<=tmax){
            int j = t*32 + lane;
            float p = p2[t];
            float4 v0 = *(const float4*)&Vsh[j*20 + 0];
            float4 v1 = *(const float4*)&Vsh[j*20 + 4];
            float4 v2 = *(const float4*)&Vsh[j*20 + 8];
            float4 v3 = *(const float4*)&Vsh[j*20 + 12];
            o[0]+=p*v0.x; o[1]+=p*v0.y; o[2]+=p*v0.z; o[3]+=p*v0.w;
            o[4]+=p*v1.x; o[5]+=p*v1.y; o[6]+=p*v1.z; o[7]+=p*v1.w;
            o[8]+=p*v2.x; o[9]+=p*v2.y; o[10]+=p*v2.z; o[11]+=p*v2.w;
            o[12]+=p*v3.x; o[13]+=p*v3.y; o[14]+=p*v3.z; o[15]+=p*v3.w;
        }
        #pragma unroll
        for (int d=0;d<16;d++){
            float v = wsum(o[d]);
            if (lane == 0) orow[w][d] = v;
        }
        __syncwarp();
        if (lane < 16) A1[((size_t)(b*SEQ + i))*DM + h*DK + lane] = orow[w][lane];
        __syncwarp();
    }
}

// ---------------- fused: P = LN(q_emb + A1@Wo^T+bo); V2 = P@Wv^T+bv ----------------
// block 256 (split-k halves), 8 rows, grid 128.
__global__ void oln1_v2_kernel(const float* __restrict__ A1,
                               const float* __restrict__ WoT, const float* __restrict__ bo,
                               const float* __restrict__ Res,
                               const float* __restrict__ lg, const float* __restrict__ lb,
                               const float* __restrict__ WvT, const float* __restrict__ bv,
                               float* __restrict__ V2)
{
    __shared__ float Ash[8*DM];
    __shared__ float Ysh[8*DM];
    __shared__ float Red[8*DM];
    const int tid = threadIdx.x;
    const int t = tid & 127, half = tid >> 7;
    const int lane = tid & 31, wid = tid >> 5;
    const int row0 = blockIdx.x * 8;

    for (int idx=tid; idx<8*DM; idx+=256)
        Ash[idx] = A1[(size_t)row0*DM + idx];
    __syncthreads();

    // phase A: A1 @ WoT over this half's k range
    float acc[8];
    #pragma unroll
    for (int r=0;r<8;r++) acc[r] = 0.f;
    {
        const int kbase = half*64;
        for (int kk=0;kk<64;kk+=8){
            int k = kbase + kk;
            float w0 = WoT[(k+0)*DM + t];
            float w1 = WoT[(k+1)*DM + t];
            float w2 = WoT[(k+2)*DM + t];
            float w3 = WoT[(k+3)*DM + t];
            float w4 = WoT[(k+4)*DM + t];
            float w5 = WoT[(k+5)*DM + t];
            float w6 = WoT[(k+6)*DM + t];
            float w7 = WoT[(k+7)*DM + t];
            #pragma unroll
            for (int r=0;r<8;r++){
                float4 a0 = *(const float4*)&Ash[r*DM + k];
                float4 a1 = *(const float4*)&Ash[r*DM + k + 4];
                acc[r] += a0.x*w0 + a0.y*w1 + a0.z*w2 + a0.w*w3
                        + a1.x*w4 + a1.y*w5 + a1.z*w6 + a1.w*w7;
            }
        }
    }
    if (half == 1){
        #pragma unroll
        for (int r=0;r<8;r++) Red[r*DM + t] = acc[r];
    }
    __syncthreads();
    if (half == 0){
        const float bov = bo[t];
        #pragma unroll
        for (int r=0;r<8;r++)
            Ysh[r*DM + t] = acc[r] + Red[r*DM + t] + bov + Res[(size_t)(row0+r)*DM + t];
    }
    __syncthreads();

    // LN per row: warp wid handles row wid (8 warps)
    {
        const int r = wid;
        float4 v = *(const float4*)&Ysh[r*DM + lane*4];
        float sg = v.x+v.y+v.z+v.w;
        float sq = v.x*v.x+v.y*v.y+v.z*v.z+v.w*v.w;
        sg = wsum(sg); sq = wsum(sq);
        float mean = sg * (1.f/128.f);
        float var  = fmaxf(sq * (1.f/128.f) - mean*mean, 0.f);
        float rstd = rsqrtf(var + 1e-5f);
        float4 g = *(const float4*)&lg[lane*4];
        float4 bb = *(const float4*)&lb[lane*4];
        v.x = (v.x-mean)*rstd*g.x + bb.x;
        v.y = (v.y-mean)*rstd*g.y + bb.y;
        v.z = (v.z-mean)*rstd*g.z + bb.z;
        v.w = (v.w-mean)*rstd*g.w + bb.w;
        *(float4*)&Ysh[r*DM + lane*4] = v;
    }
    __syncthreads();

    // phase B: P @ WvT
    #pragma unroll
    for (int r=0;r<8;r++) acc[r] = 0.f;
    {
        const int kbase = half*64;
        for (int kk=0;kk<64;kk+=8){
            int k = kbase + kk;
            float w0 = WvT[(k+0)*DM + t];
            float w1 = WvT[(k+1)*DM + t];
            float w2 = WvT[(k+2)*DM + t];
            float w3 = WvT[(k+3)*DM + t];
            float w4 = WvT[(k+4)*DM + t];
            float w5 = WvT[(k+5)*DM + t];
            float w6 = WvT[(k+6)*DM + t];
            float w7 = WvT[(k+7)*DM + t];
            #pragma unroll
            for (int r=0;r<8;r++){
                float4 a0 = *(const float4*)&Ysh[r*DM + k];
                float4 a1 = *(const float4*)&Ysh[r*DM + k + 4];
                acc[r] += a0.x*w0 + a0.y*w1 + a0.z*w2 + a0.w*w3
                        + a1.x*w4 + a1.y*w5 + a1.z*w6 + a1.w*w7;
            }
        }
    }
    __syncthreads();            // Red reuse safe
    if (half == 1){
        #pragma unroll
        for (int r=0;r<8;r++) Red[r*DM + t] = acc[r];
    }
    __syncthreads();
    if (half == 0){
        const float bvv = bv[t];
        #pragma unroll
        for (int r=0;r<8;r++)
            V2[(size_t)(row0+r)*DM + t] = acc[r] + Red[r*DM + t] + bvv;
    }
}

// ---------------- layer-2 attention ----------------
__global__ void attn2_kernel(const float* __restrict__ K2, const float* __restrict__ V2,
                             const float* __restrict__ Q2, const float* __restrict__ gamma,
                             float* __restrict__ ksc, float* __restrict__ A2)
{
    __shared__ __align__(16) float KshT[DK*SEQ];
    __shared__ __align__(16) float Vsh[SEQ*20];
    __shared__ float ss[SEQ];
    __shared__ float Ce[SEQ];
    __shared__ float wred[8];
    __shared__ float orow[8][16];

    const int bid = blockIdx.x;
    const int b = bid >> 7, n = (bid >> 3) & 15, h = bid & 7;
    const int tid = threadIdx.x, lane = tid & 31, w = tid >> 5;

    for (int idx=tid; idx<SEQ*DK; idx+=256){
        int j = idx >> 4, d = idx & 15;
        size_t g = (size_t)(b*SEQ + j)*DM + h*DK + d;
        KshT[d*SEQ + j] = K2[g];
        Vsh[j*20 + d]   = V2[g];
    }
    __syncthreads();

    float q[DK];
    #pragma unroll
    for (int d=0;d<DK;d++) q[d] = Q2[n*DM + h*DK + d];

    float s = 0.f;
    #pragma unroll
    for (int d=0;d<DK;d++) s += q[d]*KshT[d*SEQ + tid];
    s *= 0.25f;
    ss[tid] = s;

    float m = wmax(s);
    if (lane == 0) wred[w] = m;
    __syncthreads();
    float bmax = wred[0];
    #pragma unroll
    for (int k=1;k<8;k++) bmax = fmaxf(bmax, wred[k]);
    float e = expf(s - bmax);
    float x = wscan_incl(e, lane);
    __syncthreads();
    if (lane == 31) wred[w] = x;
    __syncthreads();
    float off = 0.f;
    for (int k=0;k<w;k++) off += wred[k];
    Ce[tid] = x + off;
    __syncthreads();

    const float gdec = fabsf(gamma[h]);

    for (int r=0;r<32;r++){
        const int i = w + 8*r;
        float* krow = ksc + (((size_t)(b*NH + h)*SEQ + i)*NKN + n)*SEQ;
        if (i == 0){
            #pragma unroll
            for (int t=0;t<8;t++) krow[t*32 + lane] = 0.f;
            if (lane < 16) A2[((size_t)((b*NKN + n)*SEQ + 0))*DM + h*DK + lane] = 0.f;
            continue;
        }
        const int last = i - 1, tmax = last >> 5;
        const float invS = 1.0f / Ce[last];

        float sc2[8];
        float m2 = NEGF;
        #pragma unroll
        for (int t=0;t<8;t++) if (t<=tmax){
            int j = t*32 + lane;
            float rem = fmaxf(1.0f - Ce[j]*invS, 0.f);
            float pos = fabsf((float)(i - j));
            float dist = sqrtf(rem * pos);
            float eff = expf(-gdec * dist);
            eff = fminf(fmaxf(eff, 1e-5f), 1e5f);
            float v = ss[j] * eff;
            sc2[t] = v;
            m2 = fmaxf(m2, (j<=last) ? v : NEGF);
        }
        m2 = wmax(m2);
        float sum2 = 0.f;
        #pragma unroll
        for (int t=0;t<8;t++) if (t<=tmax){
            int j = t*32 + lane;
            float e2 = (j<=last) ? expf(sc2[t]-m2) : 0.f;
            sc2[t] = e2; sum2 += e2;
        }
        sum2 = wsum(sum2);
        const float coef = fminf(sum2, 5.0f) / sum2;

        float o[16];
        #pragma unroll
        for (int d=0;d<16;d++) o[d] = 0.f;
        #pragma unroll
        for (int t=0;t<8;t++){
            float p = (t<=tmax) ? sc2[t]*coef : 0.f;
            krow[t*32 + lane] = p;
            if (t<=tmax){
                int j = t*32 + lane;
                float4 v0 = *(const float4*)&Vsh[j*20 + 0];
                float4 v1 = *(const float4*)&Vsh[j*20 + 4];
                float4 v2 = *(const float4*)&Vsh[j*20 + 8];
                float4 v3 = *(const float4*)&Vsh[j*20 + 12];
                o[0]+=p*v0.x; o[1]+=p*v0.y; o[2]+=p*v0.z; o[3]+=p*v0.w;
                o[4]+=p*v1.x; o[5]+=p*v1.y; o[6]+=p*v1.z; o[7]+=p*v1.w;
                o[8]+=p*v2.x; o[9]+=p*v2.y; o[10]+=p*v2.z; o[11]+=p*v2.w;
                o[12]+=p*v3.x; o[13]+=p*v3.y; o[14]+=p*v3.z; o[15]+=p*v3.w;
            }
        }
        #pragma unroll
        for (int d=0;d<16;d++){
            float v = wsum(o[d]);
            if (lane == 0) orow[w][d] = v;
        }
        __syncwarp();
        if (lane < 16) A2[((size_t)((b*NKN + n)*SEQ + i))*DM + h*DK + lane] = orow[w][lane];
        __syncwarp();
    }
}

// ---------------- out-proj + residual(know) + layernorm -> z ----------------
__global__ void outln2_kernel(const float* __restrict__ Ain, const float* __restrict__ WoT,
                              const float* __restrict__ bias, const float* __restrict__ Know,
                              const float* __restrict__ lg, const float* __restrict__ lb,
                              float* __restrict__ Z)
{
    __shared__ float Ash[8*DM];
    __shared__ float red1[4], red2[4];
    const int t = threadIdx.x, lane = t & 31, w = t >> 5;
    const int row0 = blockIdx.x * 8;

    #pragma unroll
    for (int r=0;r<8;r++)
        Ash[r*DM + t] = Ain[(size_t)(row0+r)*DM + t];
    __syncthreads();

    float acc[8];
    #pragma unroll
    for (int r=0;r<8;r++) acc[r] = 0.f;
    for (int k=0;k<DM;k+=8){
        float w0 = WoT[(k+0)*DM + t];
        float w1 = WoT[(k+1)*DM + t];
        float w2 = WoT[(k+2)*DM + t];
        float w3 = WoT[(k+3)*DM + t];
        float w4 = WoT[(k+4)*DM + t];
        float w5 = WoT[(k+5)*DM + t];
        float w6 = WoT[(k+6)*DM + t];
        float w7 = WoT[(k+7)*DM + t];
        #pragma unroll
        for (int r=0;r<8;r++){
            float4 a0 = *(const float4*)&Ash[r*DM + k];
            float4 a1 = *(const float4*)&Ash[r*DM + k + 4];
            acc[r] += a0.x*w0 + a0.y*w1 + a0.z*w2 + a0.w*w3
                    + a1.x*w4 + a1.y*w5 + a1.z*w6 + a1.w*w7;
        }
    }
    const float bv = bias[t], gv = lg[t], bb = lb[t];
    for (int r=0;r<8;r++){
        int row = row0 + r;                 // row = (b*NK + n)*SEQ + i
        int nn = (row >> 8) & 15;
        int bI = row >> 12;
        int ii = row & 255;
        float y = acc[r] + bv + Know[nn*DM + t];
        float sg = wsum(y), sq = wsum(y*y);
        if (lane == 0){ red1[w] = sg; red2[w] = sq; }
        __syncthreads();
        float tot = red1[0]+red1[1]+red1[2]+red1[3];
        float tq  = red2[0]+red2[1]+red2[2]+red2[3];
        __syncthreads();
        float mean = tot * (1.f/128.f);
        float var  = fmaxf(tq * (1.f/128.f) - mean*mean, 0.f);
        float outv = (y - mean) * rsqrtf(var + 1e-5f) * gv + bb;
        Z[((size_t)(bI*SEQ + ii))*(NKN*DM) + nn*DM + t] = outv;
    }
}

// ---------------- launch ----------------
extern "C" void kernel_launch(void* const* d_in, const int* in_sizes, int n_in,
                              void* d_out, int out_size)
{
    const float* q_emb   = (const float*)d_in[0];
    const float* s_emb   = (const float*)d_in[1];
    const float* b1_Wq   = (const float*)d_in[3];
    const float* b1_bq   = (const float*)d_in[4];
    const float* b1_Wv   = (const float*)d_in[5];
    const float* b1_bv   = (const float*)d_in[6];
    const float* b1_Wo   = (const float*)d_in[7];
    const float* b1_bo   = (const float*)d_in[8];
    const float* b1_gam  = (const float*)d_in[9];
    const float* b1_lng  = (const float*)d_in[10];
    const float* b1_lnb  = (const float*)d_in[11];
    const float* b4_Wq   = (const float*)d_in[12];
    const float* b4_bq   = (const float*)d_in[13];
    const float* b4_Wk   = (const float*)d_in[14];
    const float* b4_bk   = (const float*)d_in[15];
    const float* b4_Wv   = (const float*)d_in[16];
    const float* b4_bv   = (const float*)d_in[17];
    const float* b4_Wo   = (const float*)d_in[18];
    const float* b4_bo   = (const float*)d_in[19];
    const float* b4_gam  = (const float*)d_in[20];
    const float* b4_lng  = (const float*)d_in[21];
    const float* b4_lnb  = (const float*)d_in[22];
    const float* know    = (const float*)d_in[23];

    float* out = (float*)d_out;
    float* z   = out;                                     // [BS,S,NK*D]
    float* qsc = out + (size_t)BSZ*SEQ*NKN*DM;            // [BS,H,S,S]
    float* ksc = qsc + (size_t)BSZ*NH*SEQ*SEQ;            // [BS,H,S,NK,S]

    float *pQ1,*pV1,*pA1,*pK2,*pV2,*pQ2,*pA2,*pWT;
    cudaGetSymbolAddress((void**)&pQ1, g_Q1);
    cudaGetSymbolAddress((void**)&pV1, g_V1);
    cudaGetSymbolAddress((void**)&pA1, g_A1);
    cudaGetSymbolAddress((void**)&pK2, g_K2);
    cudaGetSymbolAddress((void**)&pV2, g_V2);
    cudaGetSymbolAddress((void**)&pQ2, g_Q2);
    cudaGetSymbolAddress((void**)&pA2, g_A2);
    cudaGetSymbolAddress((void**)&pWT, g_WT);

    const int MROWS = BSZ*SEQ;  // 1024

    // 0: transpose all weights (0:b1_Wq 1:b1_Wv 2:b1_Wo 3:b4_Wq 4:b4_Wk 5:b4_Wv 6:b4_Wo)
    WPtrs wp;
    wp.w[0]=b1_Wq; wp.w[1]=b1_Wv; wp.w[2]=b1_Wo; wp.w[3]=b4_Wq;
    wp.w[4]=b4_Wk; wp.w[5]=b4_Wv; wp.w[6]=b4_Wo;
    wt_kernel<<<dim3(16,7), dim3(32,8)>>>(wp, pWT);

    // 1: input-only projections in ONE launch: Q1(=K1), V1, K2, Q2
    ProjSet sQ1 = { q_emb, 0, b1_bq, pQ1, MROWS };
    ProjSet sV1 = { s_emb, 1, b1_bv, pV1, MROWS };
    ProjSet sK2 = { q_emb, 4, b4_bk, pK2, MROWS };
    ProjSet sQ2 = { know,  3, b4_bq, pQ2, NKN   };
    proj4_kernel<<<dim3(MROWS/8, 4), 128>>>(sQ1, sV1, sK2, sQ2, pWT);

    // 2: layer-1 attention
    attn1_kernel<<<dim3(8,32), 256>>>(pQ1, pV1, b1_gam, qsc, pA1);

    // 3: fused outln1 + V2 projection
    oln1_v2_kernel<<<MROWS/8, 256>>>(pA1, pWT + 2*DM*DM, b1_bo, q_emb,
                                     b1_lng, b1_lnb, pWT + 5*DM*DM, b4_bv, pV2);

    // 4: layer-2 attention
    attn2_kernel<<<512, 256>>>(pK2, pV2, pQ2, b4_gam, ksc, pA2);

    // 5: epilogue
    outln2_kernel<<<(BSZ*NKN*SEQ)/8, 128>>>(pA2, pWT + 6*DM*DM, b4_bo, know,
                                            b4_lng, b4_lnb, z);
}